// round 16
// baseline (speedup 1.0000x reference)
#include <cuda_runtime.h>
#include <cstdint>

#define HDIM 1024
#define VDIM 128
#define NS   7          // K-splits: 3 chunks of 128 + 4 chunks of 160
#define NT   20         // row tiles: 16 enc + 4 dec, 128 rows each
#define STR  36         // smem row stride in 4B words (conflict-free frags)

// Split-K fp32 partials; reduced+exp'd results
__device__ __align__(16) float g_Ep[NS * 2048 * VDIM];   // 7.3 MB
__device__ __align__(16) float g_Dp[NS * 512 * VDIM];    // 1.8 MB
__device__ __align__(16) float g_E[2048 * VDIM];         // exp(enc@W^T)
__device__ __align__(16) float g_D[512 * VDIM];          // exp(dec@W^T + b)

__device__ __forceinline__ uint32_t f2tf32(float x) {
    uint32_t r;
    asm("cvt.rna.tf32.f32 %0, %1;" : "=r"(r) : "f"(x));
    return r;
}
__device__ __forceinline__ void mma_tf32(float* d, const uint32_t* a,
                                         const uint32_t* b) {
    asm volatile(
        "mma.sync.aligned.m16n8k8.row.col.f32.tf32.tf32.f32 "
        "{%0,%1,%2,%3}, {%4,%5,%6,%7}, {%8,%9}, {%0,%1,%2,%3};"
        : "+f"(d[0]), "+f"(d[1]), "+f"(d[2]), "+f"(d[3])
        : "r"(a[0]), "r"(a[1]), "r"(a[2]), "r"(a[3]), "r"(b[0]), "r"(b[1]));
}
__device__ __forceinline__ void cp16(uint32_t dst, const void* src) {
    asm volatile("cp.async.cg.shared.global [%0], [%1], 16;" :: "r"(dst), "l"(src));
}

#define TW (128 * STR)                     // words per raw tile (A or W)
#define BUF_WORDS (2 * TW)                 // A | W
#define SMEM_DYN (3 * BUF_WORDS * 4)       // 3-stage pipeline = 110592 B

// ---------------------------------------------------------------------------
// 3xTF32 split-K GEMM, cp.async 3-stage pipeline. Grid 140 = 7 splits x 20
// tiles, 512 threads, 1 CTA/SM. CTA tile 128x128, K-chunk 32.
// RAW fp32 tiles stream GMEM->SMEM via cp.async (no register transit, no STS
// phase); the tf32 hi/lo split happens at fragment-load time in registers.
// Warp tile 32x32 = 2x4 m16n8k8, pass-major MMA order.
// ---------------------------------------------------------------------------
__global__ __launch_bounds__(512) void joint_gemm_mma(
    const float* __restrict__ enc, const float* __restrict__ dec,
    const float* __restrict__ Wt)
{
    extern __shared__ __align__(16) float sm[];

    const int s    = blockIdx.x / NT;
    const int tile = blockIdx.x - s * NT;
    const int nch  = (s < 3) ? 4 : 5;
    const int k_lo = (s < 3) ? s * 128 : 384 + (s - 3) * 160;

    const bool is_dec = (tile >= 16);
    const float* A = is_dec ? dec : enc;
    const int row0 = (is_dec ? tile - 16 : tile) * 128;
    float* Cp = is_dec ? (g_Dp + s * 512 * VDIM) : (g_Ep + s * 2048 * VDIM);

    const int tid  = threadIdx.x;
    const int lane = tid & 31;
    const int warp = tid >> 5;              // 0..15
    const int warpRow = (warp >> 2) * 32;   // 4 row groups of 32
    const int warpCol = (warp & 3) * 32;    // 4 col groups of 32
    const int lr = lane >> 2;               // 0..7
    const int lc = lane & 3;                // 0..3

    // cp.async map: A and W each 1024 16B-slots, 2 per thread.
    const int st_r  = tid >> 3;             // 0..63 (+64 second slot)
    const int st_k4 = (tid & 7) << 2;

    const uint32_t smem0 = (uint32_t)__cvta_generic_to_shared(sm);

    auto issue = [&](int ck) {              // stage raw chunk ck into buf ck%3
        const int k0 = k_lo + ck * 32;
        uint32_t ab = smem0 + (uint32_t)(ck % 3) * BUF_WORDS * 4;
        uint32_t wb = ab + TW * 4;
        cp16(ab + (st_r * STR + st_k4) * 4,
             A + (long)(row0 + st_r) * HDIM + k0 + st_k4);
        cp16(ab + ((st_r + 64) * STR + st_k4) * 4,
             A + (long)(row0 + st_r + 64) * HDIM + k0 + st_k4);
        cp16(wb + (st_r * STR + st_k4) * 4,
             Wt + (long)st_r * HDIM + k0 + st_k4);
        cp16(wb + ((st_r + 64) * STR + st_k4) * 4,
             Wt + (long)(st_r + 64) * HDIM + k0 + st_k4);
    };

    float acc[2][4][4];
    #pragma unroll
    for (int mi = 0; mi < 2; mi++)
        #pragma unroll
        for (int ni = 0; ni < 4; ni++)
            #pragma unroll
            for (int q = 0; q < 4; q++) acc[mi][ni][q] = 0.0f;

    // Prologue: fill the 3 pipeline stages (guarded; empty commits are legal).
    issue(0); asm volatile("cp.async.commit_group;");
    if (1 < nch) issue(1);
    asm volatile("cp.async.commit_group;");
    if (2 < nch) issue(2);
    asm volatile("cp.async.commit_group;");

    for (int ck = 0; ck < nch; ck++) {
        asm volatile("cp.async.wait_group 2;");   // chunk ck's buffer ready
        __syncthreads();
        const float* Ar = sm + (ck % 3) * BUF_WORDS;
        const float* Wr = Ar + TW;

        #pragma unroll
        for (int ks = 0; ks < 4; ks++) {
            const int kk = ks * 8;
            // Raw fragments from smem, then split hi/lo in registers.
            float ar[2][4], wr[4][2];
            #pragma unroll
            for (int mi = 0; mi < 2; mi++) {
                int rb = (warpRow + mi * 16 + lr) * STR + kk + lc;
                ar[mi][0] = Ar[rb];
                ar[mi][1] = Ar[rb + 8 * STR];
                ar[mi][2] = Ar[rb + 4];
                ar[mi][3] = Ar[rb + 8 * STR + 4];
            }
            #pragma unroll
            for (int ni = 0; ni < 4; ni++) {
                int nb = (warpCol + ni * 8 + lr) * STR + kk + lc;
                wr[ni][0] = Wr[nb];
                wr[ni][1] = Wr[nb + 4];
            }
            uint32_t ah[2][4], al[2][4], wh[4][2], wl[4][2];
            #pragma unroll
            for (int mi = 0; mi < 2; mi++)
                #pragma unroll
                for (int q = 0; q < 4; q++) {
                    ah[mi][q] = f2tf32(ar[mi][q]);
                    al[mi][q] = f2tf32(ar[mi][q] - __uint_as_float(ah[mi][q]));
                }
            #pragma unroll
            for (int ni = 0; ni < 4; ni++)
                #pragma unroll
                for (int q = 0; q < 2; q++) {
                    wh[ni][q] = f2tf32(wr[ni][q]);
                    wl[ni][q] = f2tf32(wr[ni][q] - __uint_as_float(wh[ni][q]));
                }
            // Pass-major: 8 independent accumulators between reuses.
            #pragma unroll
            for (int mi = 0; mi < 2; mi++)
                #pragma unroll
                for (int ni = 0; ni < 4; ni++)
                    mma_tf32(acc[mi][ni], al[mi], wh[ni]);   // low-order first
            #pragma unroll
            for (int mi = 0; mi < 2; mi++)
                #pragma unroll
                for (int ni = 0; ni < 4; ni++)
                    mma_tf32(acc[mi][ni], ah[mi], wl[ni]);
            #pragma unroll
            for (int mi = 0; mi < 2; mi++)
                #pragma unroll
                for (int ni = 0; ni < 4; ni++)
                    mma_tf32(acc[mi][ni], ah[mi], wh[ni]);
        }
        __syncthreads();                    // all reads of buf ck%3 done
        if (ck + 3 < nch) issue(ck + 3);    // refill the freed stage
        asm volatile("cp.async.commit_group;");
    }

    // Epilogue: (c, c+1) adjacent -> float2 stores.
    #pragma unroll
    for (int mi = 0; mi < 2; mi++) {
        long rg = row0 + warpRow + mi * 16 + lr;
        #pragma unroll
        for (int ni = 0; ni < 4; ni++) {
            int c = warpCol + ni * 8 + lc * 2;
            *(float2*)&Cp[rg * VDIM + c] =
                make_float2(acc[mi][ni][0], acc[mi][ni][1]);
            *(float2*)&Cp[(rg + 8) * VDIM + c] =
                make_float2(acc[mi][ni][2], acc[mi][ni][3]);
        }
    }
}

// ---------------------------------------------------------------------------
// Sum NS partials, add bias to D, store exp() of the result.
// ---------------------------------------------------------------------------
__global__ __launch_bounds__(256) void reduce_exp(const float* __restrict__ bias)
{
    int idx = blockIdx.x * 256 + threadIdx.x;
    if (idx < 65536) {                 // E: 65536 float4 outputs
        const float4* p = (const float4*)g_Ep;
        float4 a = p[idx];
        #pragma unroll
        for (int s = 1; s < NS; s++) {
            float4 v = p[idx + s * 65536];
            a.x += v.x; a.y += v.y; a.z += v.z; a.w += v.w;
        }
        ((float4*)g_E)[idx] = make_float4(__expf(a.x), __expf(a.y),
                                          __expf(a.z), __expf(a.w));
    } else {                           // D: 16384 float4 outputs
        int j = idx - 65536;
        const float4* p = (const float4*)g_Dp;
        float4 a = ((const float4*)bias)[j & 31];
        #pragma unroll
        for (int s = 0; s < NS; s++) {
            float4 v = p[j + s * 16384];
            a.x += v.x; a.y += v.y; a.z += v.z; a.w += v.w;
        }
        ((float4*)g_D)[j] = make_float4(__expf(a.x), __expf(a.y),
                                        __expf(a.z), __expf(a.w));
    }
}

// ---------------------------------------------------------------------------
// Softmax: block covers 4 bt x 8 u (32 rows). Warp handles 4 rows sharing
// one E row; D rows L1-reused across the block's 4 t values.
// ---------------------------------------------------------------------------
__global__ __launch_bounds__(256) void softmax_kernel(float* __restrict__ out)
{
    const int warp = threadIdx.x >> 5;
    const int lane = threadIdx.x & 31;
    const int btg = blockIdx.x >> 3;
    const int ug  = blockIdx.x & 7;
    const int bt  = btg * 4 + (warp >> 1);
    const int b   = bt >> 8;
    const int u0  = ug * 8 + (warp & 1) * 4;

    float4 ev = ((const float4*)g_E)[bt * 32 + lane];
    const float4* Dr = (const float4*)g_D + ((b << 6) + u0) * 32;

    float4 p[4];
    float  sum[4];
    #pragma unroll
    for (int k = 0; k < 4; k++) {
        float4 dv = Dr[k * 32 + lane];
        p[k].x = ev.x * dv.x; p[k].y = ev.y * dv.y;
        p[k].z = ev.z * dv.z; p[k].w = ev.w * dv.w;
        sum[k] = (p[k].x + p[k].y) + (p[k].z + p[k].w);
    }
    #pragma unroll
    for (int sh = 16; sh > 0; sh >>= 1) {
        #pragma unroll
        for (int k = 0; k < 4; k++)
            sum[k] += __shfl_xor_sync(0xffffffffu, sum[k], sh);
    }
    float4* o = (float4*)out + ((long)bt * 64 + u0) * 32;
    #pragma unroll
    for (int k = 0; k < 4; k++) {
        float inv = __fdividef(1.0f, sum[k]);
        o[k * 32 + lane] = make_float4(p[k].x * inv, p[k].y * inv,
                                       p[k].z * inv, p[k].w * inv);
    }
}

// ---------------------------------------------------------------------------
extern "C" void kernel_launch(void* const* d_in, const int* in_sizes, int n_in,
                              void* d_out, int out_size)
{
    const float* enc = (const float*)d_in[0];  // [8,256,1024]
    const float* dec = (const float*)d_in[1];  // [8,64,1024]
    const float* W   = (const float*)d_in[2];  // [128,1024]
    const float* b   = (const float*)d_in[3];  // [128]
    float* out = (float*)d_out;                // [8,256,64,128]

    static int smem_set = 0;
    if (!smem_set) {
        cudaFuncSetAttribute(joint_gemm_mma,
                             cudaFuncAttributeMaxDynamicSharedMemorySize, SMEM_DYN);
        smem_set = 1;
    }
    joint_gemm_mma<<<140, 512, SMEM_DYN>>>(enc, dec, W);
    reduce_exp<<<320, 256>>>(b);
    softmax_kernel<<<4096, 256>>>(out);
}